// round 17
// baseline (speedup 1.0000x reference)
#include <cuda_runtime.h>

#define P      16384
#define P4     (P / 4)
#define BM     128
#define NC     10
#define KSEL   819
#define NMASK  9830
#define EQCAP  512
#define CCAP   1024
#define WCAP   4096   // k_final window-candidate capacity (u64, 32KB)

// scratch (no allocations allowed)
__device__ unsigned char g_block[BM * P];
__device__ int g_cidx[BM * NC];

// monotone uint transform for float ordering (handles tiny negative d2)
__device__ __forceinline__ unsigned int fkey(float f) {
    unsigned int u = __float_as_uint(f);
    return u ^ ((u >> 31) ? 0xFFFFFFFFu : 0x80000000u);
}

// warp-aggregated histogram increment (heavy bucket concentration)
__device__ __forceinline__ void hist_add_agg(int* hist, unsigned int bkt) {
    unsigned int m = __match_any_sync(0xFFFFFFFFu, bkt);
    int leader = __ffs(m) - 1;
    if ((int)(threadIdx.x & 31) == leader) atomicAdd(&hist[bkt], __popc(m));
}

// Warp-0 scan of the 256-bucket histogram; locates bucket holding rank.
__device__ __forceinline__ void find_bucket_warp(const int* hist, int remaining,
                                                 int* s_sb, int* s_cum) {
    int t = threadIdx.x;
    if (t < 32) {
        int v[8];
        int base = t * 8;
        #pragma unroll
        for (int j = 0; j < 8; j++) v[j] = hist[base + j];
        #pragma unroll
        for (int j = 1; j < 8; j++) v[j] += v[j - 1];
        int tot = v[7];
        int inc = tot;
        #pragma unroll
        for (int off = 1; off < 32; off <<= 1) {
            int n = __shfl_up_sync(0xFFFFFFFFu, inc, off);
            if (t >= off) inc += n;
        }
        int excl = inc - tot;
        if (excl < remaining && remaining <= inc) {
            int j = 7;
            #pragma unroll
            for (int jj = 6; jj >= 0; jj--)
                if (excl + v[jj] >= remaining) j = jj;
            *s_sb  = base + j;
            *s_cum = excl + (j ? v[j - 1] : 0);
        }
    }
}

// 4-pass radix rank-select over smem keys (byte-3 hist pre-built by caller).
template <int NTH>
__device__ unsigned int radix_select_from_hist(const unsigned int* keys, int r,
                                               int* hist, int* s_sb, int* s_cum,
                                               int* p_ties) {
    int t = threadIdx.x;
    __syncthreads();
    find_bucket_warp(hist, r, s_sb, s_cum);
    __syncthreads();
    unsigned int prefix = ((unsigned int)*s_sb) << 24;
    int remaining = r - *s_cum;
    const uint4* k4 = (const uint4*)keys;
    for (int shift = 16; shift >= 0; shift -= 8) {
        if (t < 256) hist[t] = 0;
        __syncthreads();
        int psh = shift + 8;
        for (int i = t; i < P4; i += NTH) {
            uint4 kk = k4[i];
            unsigned int ks[4] = {kk.x, kk.y, kk.z, kk.w};
            #pragma unroll
            for (int j = 0; j < 4; j++) {
                unsigned int k = ks[j];
                if ((k >> psh) == (prefix >> psh))
                    atomicAdd(&hist[(k >> shift) & 255u], 1);
            }
        }
        __syncthreads();
        find_bucket_warp(hist, remaining, s_sb, s_cum);
        __syncthreads();
        prefix |= ((unsigned int)*s_sb) << shift;
        remaining -= *s_cum;
    }
    *p_ties = remaining;
    return prefix;
}

// Kernel 1: zero block scratch; select the 10 smallest rand_centers by
// threshold-filter (+ bisection + exact-tie fallback). Set semantics.
__global__ void __launch_bounds__(1024) k_centers(const float* __restrict__ rc) {
    const int NTH = 1024;
    __shared__ unsigned long long s_cand[CCAP];
    __shared__ int s_cnt, s_nsel;
    __shared__ unsigned long long s_min;
    int b = blockIdx.x, t = threadIdx.x;

    int4 z4 = make_int4(0, 0, 0, 0);
    int4* brow4 = (int4*)(g_block + (size_t)b * P);
    for (int i = t; i < P / 16; i += NTH) brow4[i] = z4;

    const uint4* row4 = (const uint4*)(rc + (size_t)b * P);
    unsigned int thresh = 0x3B800000u;           // 2^-8: E[count]=64
    unsigned int lo = 0, hi = 0x3F800000u;
    int cnt = 0, iter = 0;
    bool degenerate = false;
    while (true) {
        if (t == 0) s_cnt = 0;
        __syncthreads();
        for (int i = t; i < P4; i += NTH) {
            uint4 kk = row4[i];
            unsigned int ks[4] = {kk.x, kk.y, kk.z, kk.w};
            #pragma unroll
            for (int j = 0; j < 4; j++) {
                if (ks[j] < thresh) {
                    int pos = atomicAdd(&s_cnt, 1);
                    if (pos < CCAP)
                        s_cand[pos] = ((unsigned long long)ks[j] << 32) | (unsigned int)(i * 4 + j);
                }
            }
        }
        __syncthreads();
        cnt = s_cnt;
        if (cnt >= NC && cnt <= CCAP) break;
        if (cnt < NC) lo = thresh; else hi = thresh;
        if (hi - lo <= 1 || ++iter > 40) { degenerate = true; break; }
        thresh = lo + ((hi - lo) >> 1);
        __syncthreads();
    }

    int* cidx = g_cidx + b * NC;
    if (!degenerate) {
        if (t == 0) s_nsel = 0;
        __syncthreads();
        for (int i = t; i < cnt; i += NTH) {
            unsigned long long me = s_cand[i];
            int rank = 0;
            for (int j = 0; j < cnt; j++) rank += (s_cand[j] < me);
            if (rank < NC) { int pos = atomicAdd(&s_nsel, 1); cidx[pos] = (int)(me & 0xFFFFFFFFull); }
        }
    } else {
        unsigned long long low = 0;
        for (int i = 0; i < NC; i++) {
            if (t == 0) s_min = ~0ull;
            __syncthreads();
            unsigned long long local = ~0ull;
            for (int p = t; p < P; p += NTH) {
                unsigned long long key =
                    ((unsigned long long)__float_as_uint(rc[(size_t)b * P + p]) << 32) | (unsigned int)p;
                if (key >= low && key < local) local = key;
            }
            atomicMin(&s_min, local);
            __syncthreads();
            if (t == 0) cidx[i] = (int)(s_min & 0xFFFFFFFFull);
            low = s_min + 1;
            __syncthreads();
        }
    }
}

// Kernel 2: one block per (row, center). Eager-JAX fp32 d2:
//   norms un-fused (x*x+y*y)+z*z, dot = FMA chain, d2 = (ns+nc) - rn(2*dot).
__global__ void __launch_bounds__(512) k_knn(const float* __restrict__ centers) {
    const int NTH = 512;
    extern __shared__ unsigned int s_keys[];   // P u32 (64KB)
    __shared__ int hist[256];
    __shared__ int s_sb, s_cum, s_eqcnt;
    __shared__ int s_eq[EQCAP];
    int b = blockIdx.x / NC, c = blockIdx.x % NC;
    int t = threadIdx.x;

    const float* cen = centers + (size_t)(b >> 1) * P * 3;
    int ci = g_cidx[b * NC + c];
    float sx = cen[(size_t)ci * 3 + 0];
    float sy = cen[(size_t)ci * 3 + 1];
    float sz = cen[(size_t)ci * 3 + 2];
    float ns = __fadd_rn(__fadd_rn(__fmul_rn(sx, sx), __fmul_rn(sy, sy)), __fmul_rn(sz, sz));

    if (t < 256) hist[t] = 0;
    if (t == 0) s_eqcnt = 0;
    __syncthreads();

    const uint4* c4 = (const uint4*)cen;
    uint4* sk4 = (uint4*)s_keys;
    for (int g = t; g < P4; g += NTH) {
        uint4 u0 = c4[g * 3 + 0];
        uint4 u1 = c4[g * 3 + 1];
        uint4 u2 = c4[g * 3 + 2];
        float xs[4] = {__uint_as_float(u0.x), __uint_as_float(u0.w),
                       __uint_as_float(u1.z), __uint_as_float(u2.y)};
        float ys[4] = {__uint_as_float(u0.y), __uint_as_float(u1.x),
                       __uint_as_float(u1.w), __uint_as_float(u2.z)};
        float zs[4] = {__uint_as_float(u0.z), __uint_as_float(u1.y),
                       __uint_as_float(u2.x), __uint_as_float(u2.w)};
        unsigned int kout[4];
        #pragma unroll
        for (int j = 0; j < 4; j++) {
            float x = xs[j], y = ys[j], z = zs[j];
            float nc2 = __fadd_rn(__fadd_rn(__fmul_rn(x, x), __fmul_rn(y, y)), __fmul_rn(z, z));
            float dot = __fmaf_rn(sz, z, __fmaf_rn(sy, y, __fmul_rn(sx, x)));
            float d2 = __fsub_rn(__fadd_rn(ns, nc2), __fmul_rn(2.0f, dot));
            kout[j] = fkey(d2);
        }
        sk4[g] = make_uint4(kout[0], kout[1], kout[2], kout[3]);
        #pragma unroll
        for (int j = 0; j < 4; j++) hist_add_agg(hist, kout[j] >> 24);
    }

    int ties;
    unsigned int T = radix_select_from_hist<NTH>(s_keys, KSEL, hist, &s_sb, &s_cum, &ties);

    unsigned char* brow = g_block + (size_t)b * P;
    const uint4* sk4c = (const uint4*)s_keys;
    for (int i = t; i < P4; i += NTH) {
        uint4 kk = sk4c[i];
        unsigned int ks[4] = {kk.x, kk.y, kk.z, kk.w};
        int p0 = i * 4;
        #pragma unroll
        for (int j = 0; j < 4; j++) {
            unsigned int k = ks[j];
            if (k < T) brow[p0 + j] = 1;
            else if (k == T) {
                int pos = atomicAdd(&s_eqcnt, 1);
                if (pos < EQCAP) s_eq[pos] = p0 + j;
            }
        }
    }
    __syncthreads();
    int L = s_eqcnt;
    if (L <= EQCAP) {
        for (int i = t; i < L; i += NTH) {
            int p = s_eq[i]; int rank = 0;
            for (int j = 0; j < L; j++) if (s_eq[j] < p) rank++;
            if (rank < ties) brow[p] = 1;
        }
    } else {
        for (int p = t; p < P; p += NTH) {
            if (s_keys[p] == T) {
                int rank = 0;
                for (int j = 0; j < p; j++) if (s_keys[j] == T) rank++;
                if (rank < ties) brow[p] = 1;
            }
        }
    }
}

// Kernel 3: per row, select rank = (9830 - n_block) smallest rand_mask among
// non-block positions. Keys are uniform [0,1) -> order-statistic window
// select (no histograms, ~zero atomics); radix fallback for adversarial
// inputs. Write float32 mask (0.0/1.0).
__global__ void __launch_bounds__(1024) k_final(const float* __restrict__ rm,
                                                float* __restrict__ out) {
    const int NTH = 1024;
    extern __shared__ unsigned int s_keys[];                       // P u32 (64KB)
    unsigned long long* s_cand = (unsigned long long*)(s_keys + P); // WCAP u64 (32KB)
    __shared__ int hist[256];
    __shared__ int s_sb, s_cum, s_eqcnt, s_nblk, s_cnt, s_below;
    __shared__ unsigned long long s_kstar;
    __shared__ int s_eq[EQCAP];
    int b = blockIdx.x, t = threadIdx.x;

    if (t == 0) { s_eqcnt = 0; s_nblk = 0; }
    __syncthreads();

    // ---- sweep 1: build keys, count block positions ----
    const unsigned int* b4 = (const unsigned int*)(g_block + (size_t)b * P);
    const uint4* r4 = (const uint4*)(rm + (size_t)b * P);
    uint4* sk4 = (uint4*)s_keys;
    int local = 0;
    for (int i = t; i < P4; i += NTH) {
        unsigned int blk4 = b4[i];
        uint4 rr = r4[i];
        local += __popc(blk4);
        uint4 kk;
        kk.x = (blk4 & 0x000000FFu) ? 0xFFFFFFFFu : rr.x;
        kk.y = (blk4 & 0x0000FF00u) ? 0xFFFFFFFFu : rr.y;
        kk.z = (blk4 & 0x00FF0000u) ? 0xFFFFFFFFu : rr.z;
        kk.w = (blk4 & 0xFF000000u) ? 0xFFFFFFFFu : rr.w;
        sk4[i] = kk;
    }
    for (int off = 16; off; off >>= 1) local += __shfl_down_sync(0xFFFFFFFFu, local, off);
    if ((t & 31) == 0) atomicAdd(&s_nblk, local);
    __syncthreads();

    int rank = NMASK - s_nblk;         // in [1640, 9830]; M - rank = 6554 > 0
    int M = P - s_nblk;
    float q = (float)rank / (float)M;
    float halfw = 256.0f / (float)M;   // ~5 sigma; E[candidates] ~ 512

    // ---- sweeps 2..: window count + collect (uniform-CDF guess, widening) ----
    const uint4* sk4c = (const uint4*)s_keys;
    unsigned int lo = 0, hi = 0;
    int below = 0, C = 0;
    bool ok = false;
    int lane = t & 31;
    for (int att = 0; att < 3 && !ok; att++) {
        lo = __float_as_uint(fmaxf(q - halfw, 0.0f));
        hi = __float_as_uint(fminf(q + halfw, 1.0f));
        if (t == 0) { s_cnt = 0; s_below = 0; }
        __syncthreads();
        int lb = 0;
        for (int i = t; i < P4; i += NTH) {
            uint4 kk = sk4c[i];
            unsigned int ks[4] = {kk.x, kk.y, kk.z, kk.w};
            #pragma unroll
            for (int j = 0; j < 4; j++) {
                unsigned int k = ks[j];
                lb += (k < lo);
                bool take = (k >= lo) && (k < hi);
                unsigned int mask = __ballot_sync(0xFFFFFFFFu, take);
                if (mask) {
                    int leader = __ffs(mask) - 1;
                    int base;
                    if (lane == leader) base = atomicAdd(&s_cnt, __popc(mask));
                    base = __shfl_sync(0xFFFFFFFFu, base, leader);
                    if (take) {
                        int pos = base + __popc(mask & ((1u << lane) - 1u));
                        if (pos < WCAP)
                            s_cand[pos] = ((unsigned long long)k << 32) | (unsigned int)(i * 4 + j);
                    }
                }
            }
        }
        for (int off = 16; off; off >>= 1) lb += __shfl_down_sync(0xFFFFFFFFu, lb, off);
        if (lane == 0) atomicAdd(&s_below, lb);
        __syncthreads();
        below = s_below; C = s_cnt;
        if (below < rank && rank <= below + C && C <= WCAP) ok = true;
        else { halfw *= 8.0f; __syncthreads(); }
    }

    float* orow = out + (size_t)b * P;
    float4* o4 = (float4*)orow;

    if (ok) {
        // exact rank among candidates: u64 (value<<32|idx) = stable-argsort order
        int r2 = rank - below;         // >= 1
        for (int i = t; i < C; i += NTH) {
            unsigned long long me = s_cand[i];
            int rk = 0;
            for (int j = 0; j < C; j++) rk += (s_cand[j] < me);
            if (rk == r2 - 1) s_kstar = me;
        }
        __syncthreads();
        unsigned long long K = s_kstar;
        for (int i = t; i < P4; i += NTH) {
            uint4 kk = sk4c[i];
            unsigned int ks[4] = {kk.x, kk.y, kk.z, kk.w};
            float v[4];
            int p0 = i * 4;
            #pragma unroll
            for (int j = 0; j < 4; j++) {
                unsigned int k = ks[j];
                bool sel = (k == 0xFFFFFFFFu) || (k < lo) ||
                           (k < hi && ((((unsigned long long)k << 32) | (unsigned int)(p0 + j)) <= K));
                v[j] = sel ? 1.0f : 0.0f;
            }
            o4[i] = make_float4(v[0], v[1], v[2], v[3]);
        }
        return;
    }

    // ---- fallback: proven radix path (adversarial distributions) ----
    if (t < 256) hist[t] = 0;
    __syncthreads();
    for (int i = t; i < P4; i += NTH) {
        uint4 kk = sk4c[i];
        hist_add_agg(hist, kk.x >> 24);
        hist_add_agg(hist, kk.y >> 24);
        hist_add_agg(hist, kk.z >> 24);
        hist_add_agg(hist, kk.w >> 24);
    }
    int ties;
    unsigned int T = radix_select_from_hist<NTH>(s_keys, rank, hist, &s_sb, &s_cum, &ties);
    for (int i = t; i < P4; i += NTH) {
        uint4 kk = sk4c[i];
        unsigned int ks[4] = {kk.x, kk.y, kk.z, kk.w};
        float v[4];
        int p0 = i * 4;
        #pragma unroll
        for (int j = 0; j < 4; j++) {
            unsigned int k = ks[j];
            v[j] = (k == 0xFFFFFFFFu || k < T) ? 1.0f : 0.0f;
            if (k == T) {
                int pos = atomicAdd(&s_eqcnt, 1);
                if (pos < EQCAP) s_eq[pos] = p0 + j;
            }
        }
        o4[i] = make_float4(v[0], v[1], v[2], v[3]);
    }
    __syncthreads();
    int L = s_eqcnt;
    if (L <= EQCAP) {
        for (int i = t; i < L; i += NTH) {
            int p = s_eq[i]; int rank2 = 0;
            for (int j = 0; j < L; j++) if (s_eq[j] < p) rank2++;
            if (rank2 < ties) orow[p] = 1.0f;
        }
    } else {
        for (int p = t; p < P; p += NTH) {
            if (s_keys[p] == T) {
                int rank2 = 0;
                for (int j = 0; j < p; j++) if (s_keys[j] == T) rank2++;
                if (rank2 < ties) orow[p] = 1.0f;
            }
        }
    }
}

extern "C" void kernel_launch(void* const* d_in, const int* in_sizes, int n_in,
                              void* d_out, int out_size) {
    const float* centers = (const float*)d_in[0];  // [64, 16384, 3]
    const float* rc      = (const float*)d_in[1];  // [128, 16384]
    const float* rm      = (const float*)d_in[2];  // [128, 16384]
    float* out           = (float*)d_out;          // [128, 16384] float32 (bool->f32)

    const int SMEM_KNN   = P * 4;               // 64KB keys
    const int SMEM_FINAL = P * 4 + WCAP * 8;    // 64KB keys + 32KB candidates
    cudaFuncSetAttribute(k_knn,   cudaFuncAttributeMaxDynamicSharedMemorySize, SMEM_KNN);
    cudaFuncSetAttribute(k_final, cudaFuncAttributeMaxDynamicSharedMemorySize, SMEM_FINAL);

    k_centers<<<BM, 1024>>>(rc);
    k_knn<<<BM * NC, 512, SMEM_KNN>>>(centers);
    k_final<<<BM, 1024, SMEM_FINAL>>>(rm, out);
}